// round 4
// baseline (speedup 1.0000x reference)
#include <cuda_runtime.h>

#define NPTS 8192
#define BATCH 2
#define KK 20
#define FULLMASK 0xffffffffu

// -------- device scratch (no allocations allowed) --------
__device__ float g_xx[BATCH * NPTS];
__device__ int   g_idx[BATCH * NPTS * KK];
__device__ float g_pre[BATCH * NPTS * 64];   // per-point neighbor term (per layer)
__device__ float g_ctr[BATCH * NPTS * 64];   // per-point center term (per layer)
__device__ float g_cat[BATCH * NPTS * 192];  // point-major concat of x1|x2|x3

__device__ __forceinline__ float leaky(float v) { return fmaxf(v, 0.2f * v); }

// packed f32x2 fused multiply-add (Blackwell: PTX-only, 2 MACs per fma-pipe issue)
__device__ __forceinline__ void fma2(unsigned long long& d, unsigned long long a,
                                     unsigned long long b) {
    asm("fma.rn.f32x2 %0, %1, %2, %0;" : "+l"(d) : "l"(a), "l"(b));
}
__device__ __forceinline__ float2 unpack2(unsigned long long v) {
    float lo, hi;
    asm("mov.b64 {%0, %1}, %2;" : "=f"(lo), "=f"(hi) : "l"(v));
    return make_float2(lo, hi);
}

// -------- squared norms of xyz --------
__global__ void xx_kernel(const float* __restrict__ x) {
    int id = blockIdx.x * 256 + threadIdx.x;  // 0..16383
    int b = id >> 13, j = id & (NPTS - 1);
    const float* xb = x + b * 6 * NPTS;
    float a = xb[j], c = xb[NPTS + j], e = xb[2 * NPTS + j];
    g_xx[id] = a * a + c * c + e * e;
}

// sorted-list push: list ascending over lanes 0..19 (lane0 = min), +inf in lanes 20..31.
// Insert ce (known > mnv) evicting the min; mnv updated. ~40cyc chain, no REDUX.
__device__ __forceinline__ void push_sorted(int lane, float ce, int cj,
                                            float& key, int& kj, float& mnv) {
    float dn  = __shfl_down_sync(FULLMASK, key, 1);
    int   dnj = __shfl_down_sync(FULLMASK, kj, 1);
    float sec = __shfl_sync(FULLMASK, key, 1);
    unsigned bal = __ballot_sync(FULLMASK, key < ce);
    int p = __popc(bal) - 1;
    if (lane == p) { key = ce; kj = cj; }
    else if (lane < p) { key = dn; kj = dnj; }
    mnv = (p == 0) ? ce : sec;
}

// -------- KNN: 4 queries/warp, sorted top-20 list per query --------
__global__ __launch_bounds__(256) void knn_kernel(const float* __restrict__ x) {
    __shared__ float4 tile[2048];
    const int b = blockIdx.y;
    const int warp = threadIdx.x >> 5;
    const int lane = threadIdx.x & 31;
    const int qbase = blockIdx.x * 32 + warp * 4;
    const float* xb = x + b * 6 * NPTS;
    const float* xxb = g_xx + b * NPTS;

    float qx[4], qy[4], qz[4];
#pragma unroll
    for (int q = 0; q < 4; ++q) {
        int n = qbase + q;
        qx[q] = xb[n]; qy[q] = xb[NPTS + n]; qz[q] = xb[2 * NPTS + n];
    }

    float key[4]; int kj[4]; float mnv[4]; float e4[4];

    // ---- prefill: candidates j = lane (0..31); lanes 0..19 seed the list ----
    {
        float cx = xb[lane], cy = xb[NPTS + lane], cz = xb[2 * NPTS + lane];
        float cw = xxb[lane];
#pragma unroll
        for (int q = 0; q < 4; ++q) {
            float dot = fmaf(qx[q], cx, fmaf(qy[q], cy, qz[q] * cz));
            float e = fmaf(-0.5f, cw, dot);
            e4[q] = e;
            key[q] = (lane < KK) ? e : __int_as_float(0x7f800000);  // +inf pad
            kj[q] = lane;
        }
        // warp bitonic sort ascending (key, kj) per query
#pragma unroll
        for (int q = 0; q < 4; ++q) {
#pragma unroll
            for (int k2 = 2; k2 <= 32; k2 <<= 1) {
#pragma unroll
                for (int jj = k2 >> 1; jj > 0; jj >>= 1) {
                    float ok = __shfl_xor_sync(FULLMASK, key[q], jj);
                    int   ov = __shfl_xor_sync(FULLMASK, kj[q], jj);
                    bool lower = ((lane & jj) == 0);
                    bool asc = ((lane & k2) == 0);
                    bool takeMin = (lower == asc);
                    bool sel = takeMin ? (ok < key[q]) : (ok > key[q]);
                    if (sel) { key[q] = ok; kj[q] = ov; }
                }
            }
            mnv[q] = __shfl_sync(FULLMASK, key[q], 0);
        }
        // push candidates j = 20..31 (carried by lanes 20..31)
#pragma unroll
        for (int q = 0; q < 4; ++q) {
            unsigned mask = __ballot_sync(FULLMASK, (lane >= KK) && (e4[q] > mnv[q]));
            while (mask) {
                int src = __ffs(mask) - 1; mask &= mask - 1;
                float ce = __shfl_sync(FULLMASK, e4[q], src);
                if (ce > mnv[q]) push_sorted(lane, ce, src, key[q], kj[q], mnv[q]);
            }
        }
    }

    // ---- main streaming loop over smem tiles ----
    for (int t = 0; t < NPTS; t += 2048) {
        __syncthreads();
        for (int i = threadIdx.x; i < 2048; i += 256) {
            int j = t + i;
            tile[i] = make_float4(xb[j], xb[NPTS + j], xb[2 * NPTS + j], xxb[j]);
        }
        __syncthreads();
        int istart = (t == 0) ? (32 + lane) : lane;
        for (int i = istart; i < 2048; i += 32) {
            float4 c = tile[i];
            int j = t + i;
            float ed[4];
            float hw = -0.5f * c.w;
#pragma unroll
            for (int q = 0; q < 4; ++q) {
                float dot = fmaf(qx[q], c.x, fmaf(qy[q], c.y, qz[q] * c.z));
                ed[q] = dot + hw;
            }
            bool pr0 = ed[0] > mnv[0], pr1 = ed[1] > mnv[1];
            bool pr2 = ed[2] > mnv[2], pr3 = ed[3] > mnv[3];
            if (__any_sync(FULLMASK, pr0 | pr1 | pr2 | pr3)) {
                bool prq[4] = {pr0, pr1, pr2, pr3};
#pragma unroll
                for (int q = 0; q < 4; ++q) {
                    unsigned mask = __ballot_sync(FULLMASK, prq[q]);
                    while (mask) {
                        int src = __ffs(mask) - 1; mask &= mask - 1;
                        float ce = __shfl_sync(FULLMASK, ed[q], src);
                        int   cj = __shfl_sync(FULLMASK, j, src);
                        if (ce > mnv[q]) push_sorted(lane, ce, cj, key[q], kj[q], mnv[q]);
                    }
                }
            }
        }
    }

#pragma unroll
    for (int q = 0; q < 4; ++q)
        if (lane < KK) g_idx[(b * NPTS + qbase + q) * KK + lane] = kj[q];
}

// -------- conv1 pre --------
__global__ __launch_bounds__(256) void pre1_kernel(const float* __restrict__ x,
                                                   const float* __restrict__ W1) {
    __shared__ float sW[384];
    for (int t = threadIdx.x; t < 384; t += 256)
        sW[t] = W1[t] * (((t % 6) < 3) ? 10.0f : 1.0f);
    __syncthreads();
    int o = threadIdx.x & 63;
    int pid = blockIdx.x * 4 + (threadIdx.x >> 6);
    int b = pid >> 13, j = pid & (NPTS - 1);
    const float* xb = x + b * 6 * NPTS;
    float acc = 0.f;
#pragma unroll
    for (int c = 0; c < 6; ++c) acc = fmaf(sW[o * 6 + c], xb[c * NPTS + j], acc);
    g_pre[pid * 64 + o] = acc;
}

// -------- conv1 gather-max (lane-held idx + shfl distribution) --------
__global__ __launch_bounds__(256) void conv1_kernel(const float* __restrict__ x,
                                                    const float* __restrict__ W1,
                                                    const float* __restrict__ b1) {
    int b = blockIdx.y;
    int lane = threadIdx.x & 31;
    int n = blockIdx.x * 8 + (threadIdx.x >> 5);
    int pid = b * NPTS + n;
    int jk = 0; float mx = 0.f, my = 0.f, mz = 0.f;
    if (lane < KK) {
        jk = g_idx[pid * KK + lane];
        const float* xb = x + b * 6 * NPTS;
        mx = xb[jk]; my = xb[NPTS + jk]; mz = xb[2 * NPTS + jk];
    }
#pragma unroll
    for (int off = 16; off; off >>= 1) {
        mx += __shfl_xor_sync(FULLMASK, mx, off);
        my += __shfl_xor_sync(FULLMASK, my, off);
        mz += __shfl_xor_sync(FULLMASK, mz, off);
    }
    float m0 = mx / (float)KK, m1 = my / (float)KK, m2 = mz / (float)KK;
    int o0 = lane, o1 = lane + 32;
    float c0 = b1[o0] - 10.0f * (W1[o0 * 6] * m0 + W1[o0 * 6 + 1] * m1 + W1[o0 * 6 + 2] * m2);
    float c1 = b1[o1] - 10.0f * (W1[o1 * 6] * m0 + W1[o1 * 6 + 1] * m1 + W1[o1 * 6 + 2] * m2);
    float v0 = -1e30f, v1 = -1e30f;
    const float* pb = g_pre + b * NPTS * 64;
#pragma unroll
    for (int k = 0; k < KK; ++k) {
        int j = __shfl_sync(FULLMASK, jk, k);
        const float* p = pb + j * 64 + lane;
        v0 = fmaxf(v0, p[0]);
        v1 = fmaxf(v1, p[32]);
    }
    float* cp = g_cat + pid * 192;
    cp[o0] = leaky(v0 + c0);
    cp[o1] = leaky(v1 + c1);
}

// -------- conv2/3 pre with FFMA2: acc pair = (Wa@x, (Wb-Wa)@x) --------
__global__ __launch_bounds__(256) void preC_kernel(const float* __restrict__ W,
                                                   const float* __restrict__ bias,
                                                   int in_off) {
    __shared__ float2 sWp[64][65];   // (wa, wd)
    __shared__ float2 sX2[32][64];   // (x, x)
    for (int t = threadIdx.x; t < 4096; t += 256) {
        int oo = t >> 6, cc = t & 63;
        float wa = W[oo * 128 + cc];
        float wd = W[oo * 128 + 64 + cc] - wa;
        sWp[oo][cc] = make_float2(wa, wd);
    }
    int p0 = blockIdx.x * 32;
    for (int t = threadIdx.x; t < 2048; t += 256) {
        int pp = t >> 6, cc = t & 63;
        float v = g_cat[(p0 + pp) * 192 + in_off + cc];
        sX2[pp][cc] = make_float2(v, v);
    }
    __syncthreads();
    int o = threadIdx.x & 63, pg = threadIdx.x >> 6;
    unsigned long long acc2[8];
#pragma unroll
    for (int i = 0; i < 8; ++i) acc2[i] = 0ull;
    for (int c = 0; c < 64; ++c) {
        unsigned long long w2 = *(const unsigned long long*)&sWp[o][c];
#pragma unroll
        for (int i = 0; i < 8; ++i) {
            unsigned long long x2 = *(const unsigned long long*)&sX2[pg + 4 * i][c];
            fma2(acc2[i], w2, x2);
        }
    }
    float bo = bias[o];
#pragma unroll
    for (int i = 0; i < 8; ++i) {
        int pid = p0 + pg + 4 * i;
        float2 ad = unpack2(acc2[i]);
        g_pre[pid * 64 + o] = ad.x;
        g_ctr[pid * 64 + o] = ad.y + bo;
    }
}

// -------- conv2/3 gather-max --------
__global__ __launch_bounds__(256) void convG_kernel(int out_off) {
    int b = blockIdx.y;
    int lane = threadIdx.x & 31;
    int n = blockIdx.x * 8 + (threadIdx.x >> 5);
    int pid = b * NPTS + n;
    int jk = (lane < KK) ? g_idx[pid * KK + lane] : 0;
    float z0 = g_ctr[pid * 64 + lane];
    float z1 = g_ctr[pid * 64 + 32 + lane];
    float v0 = -1e30f, v1 = -1e30f;
    const float* pb = g_pre + b * NPTS * 64;
#pragma unroll
    for (int k = 0; k < KK; ++k) {
        int j = __shfl_sync(FULLMASK, jk, k);
        const float* p = pb + j * 64 + lane;
        v0 = fmaxf(v0, p[0]);
        v1 = fmaxf(v1, p[32]);
    }
    float* cp = g_cat + pid * 192 + out_off;
    cp[lane] = leaky(v0 + z0);
    cp[32 + lane] = leaky(v1 + z1);
}

// -------- final GEMM with FFMA2: out = leaky(W4 @ cat + b4) --------
__global__ __launch_bounds__(256) void final_kernel(const float* __restrict__ W4,
                                                    const float* __restrict__ b4,
                                                    float* __restrict__ out) {
    __shared__ float2 sA2[16][64];   // duplicated (a,a) pairs, [c][o]
    __shared__ float  sB[16][128];
    int b = blockIdx.z;
    int obase = blockIdx.y * 64;
    int nbase = blockIdx.x * 128;
    int t = threadIdx.x;
    unsigned long long acc2[8][2];
#pragma unroll
    for (int i = 0; i < 8; ++i) { acc2[i][0] = 0ull; acc2[i][1] = 0ull; }
    int lo = t >> 2, lc = (t & 3) * 4;
    int o8l = (t >> 5) * 8, n4l = (t & 31) * 4;
    for (int c0 = 0; c0 < 192; c0 += 16) {
        float4 av = *(const float4*)(W4 + (obase + lo) * 192 + c0 + lc);
        sA2[lc + 0][lo] = make_float2(av.x, av.x);
        sA2[lc + 1][lo] = make_float2(av.y, av.y);
        sA2[lc + 2][lo] = make_float2(av.z, av.z);
        sA2[lc + 3][lo] = make_float2(av.w, av.w);
#pragma unroll
        for (int r = 0; r < 2; ++r) {
            int l = t + r * 256;
            int nn = l >> 2, cc = (l & 3) * 4;
            const float* src = g_cat + (b * NPTS + nbase + nn) * 192 + c0 + cc;
            float4 bv = *(const float4*)src;
            sB[cc + 0][nn] = bv.x; sB[cc + 1][nn] = bv.y; sB[cc + 2][nn] = bv.z; sB[cc + 3][nn] = bv.w;
        }
        __syncthreads();
#pragma unroll
        for (int c = 0; c < 16; ++c) {
            unsigned long long a2[8], b2[2];
#pragma unroll
            for (int i = 0; i < 8; ++i)
                a2[i] = *(const unsigned long long*)&sA2[c][o8l + i];
            b2[0] = *(const unsigned long long*)&sB[c][n4l];
            b2[1] = *(const unsigned long long*)&sB[c][n4l + 2];
#pragma unroll
            for (int i = 0; i < 8; ++i) {
                fma2(acc2[i][0], a2[i], b2[0]);
                fma2(acc2[i][1], a2[i], b2[1]);
            }
        }
        __syncthreads();
    }
    int o8 = obase + o8l, n4 = nbase + n4l;
#pragma unroll
    for (int i = 0; i < 8; ++i) {
        float bo = b4[o8 + i];
        float2 p0 = unpack2(acc2[i][0]);
        float2 p1 = unpack2(acc2[i][1]);
        float4 v;
        v.x = leaky(p0.x + bo);
        v.y = leaky(p0.y + bo);
        v.z = leaky(p1.x + bo);
        v.w = leaky(p1.y + bo);
        *(float4*)(out + ((long)(b * 256 + o8 + i)) * NPTS + n4) = v;
    }
}

extern "C" void kernel_launch(void* const* d_in, const int* in_sizes, int n_in,
                              void* d_out, int out_size) {
    const float* x  = (const float*)d_in[0];
    const float* W1 = (const float*)d_in[1];
    const float* b1 = (const float*)d_in[2];
    const float* W2 = (const float*)d_in[3];
    const float* b2 = (const float*)d_in[4];
    const float* W3 = (const float*)d_in[5];
    const float* b3 = (const float*)d_in[6];
    const float* W4 = (const float*)d_in[7];
    const float* b4 = (const float*)d_in[8];
    float* out = (float*)d_out;

    xx_kernel<<<64, 256>>>(x);
    knn_kernel<<<dim3(256, 2), 256>>>(x);
    pre1_kernel<<<4096, 256>>>(x, W1);
    conv1_kernel<<<dim3(1024, 2), 256>>>(x, W1, b1);
    preC_kernel<<<512, 256>>>(W2, b2, 0);
    convG_kernel<<<dim3(1024, 2), 256>>>(64);
    preC_kernel<<<512, 256>>>(W3, b3, 64);
    convG_kernel<<<dim3(1024, 2), 256>>>(128);
    final_kernel<<<dim3(64, 4, 2), 256>>>(W4, b4, out);
}

// round 5
// speedup vs baseline: 1.2453x; 1.2453x over previous
#include <cuda_runtime.h>

#define NPTS 8192
#define BATCH 2
#define KK 20
#define FULLMASK 0xffffffffu

// -------- device scratch (no allocations allowed) --------
__device__ float g_xx[BATCH * NPTS];
__device__ int   g_idx[BATCH * NPTS * KK];
__device__ float g_pre[BATCH * NPTS * 64];   // per-point neighbor term (per layer)
__device__ float g_ctr[BATCH * NPTS * 64];   // per-point center term (per layer)
__device__ float g_cat[BATCH * NPTS * 192];  // point-major concat of x1|x2|x3

__device__ __forceinline__ float leaky(float v) { return fmaxf(v, 0.2f * v); }

// monotone float <-> sortable-uint maps (order-preserving, involutive for finite floats)
__device__ __forceinline__ unsigned f2s(float f) {
    unsigned u = __float_as_uint(f);
    return u ^ (unsigned)(((int)u >> 31) | 0x80000000);
}
__device__ __forceinline__ float s2f(unsigned u) {
    unsigned x = u ^ (unsigned)(((int)(~u) >> 31) | 0x80000000);
    return __uint_as_float(x);
}

// -------- squared norms of xyz --------
__global__ void xx_kernel(const float* __restrict__ x) {
    int id = blockIdx.x * 256 + threadIdx.x;  // 0..16383
    int b = id >> 13, j = id & (NPTS - 1);
    const float* xb = x + b * 6 * NPTS;
    float a = xb[j], c = xb[NPTS + j], e = xb[2 * NPTS + j];
    g_xx[id] = a * a + c * c + e * e;
}

// -------- KNN: 4 queries per warp, streaming replace-min top-20 (REDUX push) --------
// Ranking key: e = dot(q,c) - 0.5*xx_c  (monotone in d = 2e - xx_q; xx_q const per query).
// Slots prefilled with 20 real candidates so the running min is always a real float.
__global__ __launch_bounds__(256) void knn_kernel(const float* __restrict__ x) {
    __shared__ float4 tile[2048];
    const int b = blockIdx.y;
    const int warp = threadIdx.x >> 5;
    const int lane = threadIdx.x & 31;
    const int qbase = blockIdx.x * 32 + warp * 4;   // 4 queries per warp
    const float* xb = x + b * 6 * NPTS;
    const float* xxb = g_xx + b * NPTS;

    float qx[4], qy[4], qz[4];
#pragma unroll
    for (int q = 0; q < 4; ++q) {
        int n = qbase + q;
        qx[q] = xb[n]; qy[q] = xb[NPTS + n]; qz[q] = xb[2 * NPTS + n];
    }

    unsigned kuv[4];
    int kj[4];
    float mnv[4];
    int mnl[4];

    // ---- prefill slots with candidates j = 0..19 ----
    {
        float cx = 0.f, cy = 0.f, cz = 0.f, cw = 0.f;
        if (lane < KK) {
            cx = xb[lane]; cy = xb[NPTS + lane]; cz = xb[2 * NPTS + lane];
            cw = xxb[lane];
        }
#pragma unroll
        for (int q = 0; q < 4; ++q) {
            float dot = fmaf(qx[q], cx, fmaf(qy[q], cy, qz[q] * cz));
            float e = fmaf(-0.5f, cw, dot);
            kuv[q] = (lane < KK) ? f2s(e) : 0xFFFFFFFFu;
            kj[q] = lane;
            unsigned mn = __reduce_min_sync(FULLMASK, kuv[q]);
            unsigned bal = __ballot_sync(FULLMASK, kuv[q] == mn);
            mnl[q] = __ffs(bal) - 1;
            mnv[q] = s2f(mn);
        }
    }

    // ---- process candidates j = 20..31 (lanes 20..31 carry them) ----
    {
        int j = lane;
        float cx = xb[j], cy = xb[NPTS + j], cz = xb[2 * NPTS + j], cw = xxb[j];
        bool valid = (lane >= KK);
#pragma unroll
        for (int q = 0; q < 4; ++q) {
            float dot = fmaf(qx[q], cx, fmaf(qy[q], cy, qz[q] * cz));
            float e = fmaf(-0.5f, cw, dot);
            unsigned mask = __ballot_sync(FULLMASK, valid && (e > mnv[q]));
            while (mask) {
                int src = __ffs(mask) - 1; mask &= mask - 1;
                float ce = __shfl_sync(FULLMASK, e, src);
                int   cj = __shfl_sync(FULLMASK, j, src);
                if (ce > mnv[q]) {
                    if (lane == mnl[q]) { kuv[q] = f2s(ce); kj[q] = cj; }
                    unsigned mn = __reduce_min_sync(FULLMASK, kuv[q]);
                    unsigned bal = __ballot_sync(FULLMASK, kuv[q] == mn);
                    mnl[q] = __ffs(bal) - 1;
                    mnv[q] = s2f(mn);
                }
            }
        }
    }

    // ---- main streaming loop over smem tiles ----
    for (int t = 0; t < NPTS; t += 2048) {
        __syncthreads();
        for (int i = threadIdx.x; i < 2048; i += 256) {
            int j = t + i;
            tile[i] = make_float4(xb[j], xb[NPTS + j], xb[2 * NPTS + j], xxb[j]);
        }
        __syncthreads();
        int istart = (t == 0) ? (32 + lane) : lane;
        for (int i = istart; i < 2048; i += 32) {
            float4 c = tile[i];
            int j = t + i;
            float ed[4];
            float hw = -0.5f * c.w;
#pragma unroll
            for (int q = 0; q < 4; ++q) {
                float dot = fmaf(qx[q], c.x, fmaf(qy[q], c.y, qz[q] * c.z));
                ed[q] = dot + hw;
            }
            bool pr0 = ed[0] > mnv[0], pr1 = ed[1] > mnv[1];
            bool pr2 = ed[2] > mnv[2], pr3 = ed[3] > mnv[3];
            if (__any_sync(FULLMASK, pr0 | pr1 | pr2 | pr3)) {
                bool prq[4] = {pr0, pr1, pr2, pr3};
#pragma unroll
                for (int q = 0; q < 4; ++q) {
                    unsigned mask = __ballot_sync(FULLMASK, prq[q]);
                    while (mask) {
                        int src = __ffs(mask) - 1; mask &= mask - 1;
                        float ce = __shfl_sync(FULLMASK, ed[q], src);
                        int   cj = __shfl_sync(FULLMASK, j, src);
                        if (ce > mnv[q]) {
                            if (lane == mnl[q]) { kuv[q] = f2s(ce); kj[q] = cj; }
                            unsigned mn = __reduce_min_sync(FULLMASK, kuv[q]);
                            unsigned bal = __ballot_sync(FULLMASK, kuv[q] == mn);
                            mnl[q] = __ffs(bal) - 1;
                            mnv[q] = s2f(mn);
                        }
                    }
                }
            }
        }
    }

#pragma unroll
    for (int q = 0; q < 4; ++q)
        if (lane < KK) g_idx[(b * NPTS + qbase + q) * KK + lane] = kj[q];
}

// -------- conv1 pre: p[j][o] = sum_{c<3} 10*W1[o,c]*xyz[j,c] + sum_{c>=3} W1[o,c]*x[c,j] --------
__global__ __launch_bounds__(256) void pre1_kernel(const float* __restrict__ x,
                                                   const float* __restrict__ W1) {
    __shared__ float sW[384];
    for (int t = threadIdx.x; t < 384; t += 256)
        sW[t] = W1[t] * (((t % 6) < 3) ? 10.0f : 1.0f);
    __syncthreads();
    int o = threadIdx.x & 63;
    int pid = blockIdx.x * 4 + (threadIdx.x >> 6);
    int b = pid >> 13, j = pid & (NPTS - 1);
    const float* xb = x + b * 6 * NPTS;
    float acc = 0.f;
#pragma unroll
    for (int c = 0; c < 6; ++c) acc = fmaf(sW[o * 6 + c], xb[c * NPTS + j], acc);
    g_pre[pid * 64 + o] = acc;
}

// -------- conv1 gather-max (lane-held idx + shfl distribution) --------
__global__ __launch_bounds__(256) void conv1_kernel(const float* __restrict__ x,
                                                    const float* __restrict__ W1,
                                                    const float* __restrict__ b1) {
    int b = blockIdx.y;
    int lane = threadIdx.x & 31;
    int n = blockIdx.x * 8 + (threadIdx.x >> 5);
    int pid = b * NPTS + n;
    int jk = 0; float mx = 0.f, my = 0.f, mz = 0.f;
    if (lane < KK) {
        jk = g_idx[pid * KK + lane];
        const float* xb = x + b * 6 * NPTS;
        mx = xb[jk]; my = xb[NPTS + jk]; mz = xb[2 * NPTS + jk];
    }
#pragma unroll
    for (int off = 16; off; off >>= 1) {
        mx += __shfl_xor_sync(FULLMASK, mx, off);
        my += __shfl_xor_sync(FULLMASK, my, off);
        mz += __shfl_xor_sync(FULLMASK, mz, off);
    }
    float m0 = mx / (float)KK, m1 = my / (float)KK, m2 = mz / (float)KK;
    int o0 = lane, o1 = lane + 32;
    float c0 = b1[o0] - 10.0f * (W1[o0 * 6] * m0 + W1[o0 * 6 + 1] * m1 + W1[o0 * 6 + 2] * m2);
    float c1 = b1[o1] - 10.0f * (W1[o1 * 6] * m0 + W1[o1 * 6 + 1] * m1 + W1[o1 * 6 + 2] * m2);
    float v0 = -1e30f, v1 = -1e30f;
    const float* pb = g_pre + b * NPTS * 64;
#pragma unroll
    for (int k = 0; k < KK; ++k) {
        int j = __shfl_sync(FULLMASK, jk, k);
        const float* p = pb + j * 64 + lane;
        v0 = fmaxf(v0, p[0]);
        v1 = fmaxf(v1, p[32]);
    }
    float* cp = g_cat + pid * 192;
    cp[o0] = leaky(v0 + c0);
    cp[o1] = leaky(v1 + c1);
}

// -------- conv2/3 pre: y = Wa@x, z = (Wb - Wa)@x + bias (x = cat[:, in_off:in_off+64]) --------
__global__ __launch_bounds__(256) void preC_kernel(const float* __restrict__ W,
                                                   const float* __restrict__ bias,
                                                   int in_off) {
    __shared__ float sWa[64][65];
    __shared__ float sWd[64][65];
    __shared__ float sX[32][64];
    for (int t = threadIdx.x; t < 4096; t += 256) {
        int oo = t >> 6, cc = t & 63;
        float wa = W[oo * 128 + cc];
        sWa[oo][cc] = wa;
        sWd[oo][cc] = W[oo * 128 + 64 + cc] - wa;
    }
    int p0 = blockIdx.x * 32;
    for (int t = threadIdx.x; t < 2048; t += 256) {
        int pp = t >> 6, cc = t & 63;
        sX[pp][cc] = g_cat[(p0 + pp) * 192 + in_off + cc];
    }
    __syncthreads();
    int o = threadIdx.x & 63, pg = threadIdx.x >> 6;
    float aA[8], aD[8];
#pragma unroll
    for (int i = 0; i < 8; ++i) { aA[i] = 0.f; aD[i] = 0.f; }
    for (int c = 0; c < 64; ++c) {
        float wa = sWa[o][c], wd = sWd[o][c];
#pragma unroll
        for (int i = 0; i < 8; ++i) {
            float xv = sX[pg + 4 * i][c];
            aA[i] = fmaf(wa, xv, aA[i]);
            aD[i] = fmaf(wd, xv, aD[i]);
        }
    }
    float bo = bias[o];
#pragma unroll
    for (int i = 0; i < 8; ++i) {
        int pid = p0 + pg + 4 * i;
        g_pre[pid * 64 + o] = aA[i];
        g_ctr[pid * 64 + o] = aD[i] + bo;
    }
}

// -------- conv2/3 gather-max (lane-held idx + shfl distribution) --------
__global__ __launch_bounds__(256) void convG_kernel(int out_off) {
    int b = blockIdx.y;
    int lane = threadIdx.x & 31;
    int n = blockIdx.x * 8 + (threadIdx.x >> 5);
    int pid = b * NPTS + n;
    int jk = (lane < KK) ? g_idx[pid * KK + lane] : 0;
    float z0 = g_ctr[pid * 64 + lane];
    float z1 = g_ctr[pid * 64 + 32 + lane];
    float v0 = -1e30f, v1 = -1e30f;
    const float* pb = g_pre + b * NPTS * 64;
#pragma unroll
    for (int k = 0; k < KK; ++k) {
        int j = __shfl_sync(FULLMASK, jk, k);
        const float* p = pb + j * 64 + lane;
        v0 = fmaxf(v0, p[0]);
        v1 = fmaxf(v1, p[32]);
    }
    float* cp = g_cat + pid * 192 + out_off;
    cp[lane] = leaky(v0 + z0);
    cp[32 + lane] = leaky(v1 + z1);
}

// -------- final: out[b,o,n] = leaky(W4 @ cat + b4), M=256 K=192 (scalar FFMA) --------
__global__ __launch_bounds__(256) void final_kernel(const float* __restrict__ W4,
                                                    const float* __restrict__ b4,
                                                    float* __restrict__ out) {
    __shared__ float sA[16][64];
    __shared__ float sB[16][128];
    int b = blockIdx.z;
    int obase = blockIdx.y * 64;
    int nbase = blockIdx.x * 128;
    int t = threadIdx.x;
    float acc[8][4];
#pragma unroll
    for (int i = 0; i < 8; ++i)
#pragma unroll
        for (int jq = 0; jq < 4; ++jq) acc[i][jq] = 0.f;
    int lo = t >> 2, lc = (t & 3) * 4;
    int o8l = (t >> 5) * 8, n4l = (t & 31) * 4;
    for (int c0 = 0; c0 < 192; c0 += 16) {
        float4 av = *(const float4*)(W4 + (obase + lo) * 192 + c0 + lc);
        sA[lc + 0][lo] = av.x; sA[lc + 1][lo] = av.y; sA[lc + 2][lo] = av.z; sA[lc + 3][lo] = av.w;
#pragma unroll
        for (int r = 0; r < 2; ++r) {
            int l = t + r * 256;
            int nn = l >> 2, cc = (l & 3) * 4;
            const float* src = g_cat + (b * NPTS + nbase + nn) * 192 + c0 + cc;
            float4 bv = *(const float4*)src;
            sB[cc + 0][nn] = bv.x; sB[cc + 1][nn] = bv.y; sB[cc + 2][nn] = bv.z; sB[cc + 3][nn] = bv.w;
        }
        __syncthreads();
#pragma unroll
        for (int c = 0; c < 16; ++c) {
            float a[8], bb[4];
#pragma unroll
            for (int i = 0; i < 8; ++i) a[i] = sA[c][o8l + i];
#pragma unroll
            for (int jq = 0; jq < 4; ++jq) bb[jq] = sB[c][n4l + jq];
#pragma unroll
            for (int i = 0; i < 8; ++i)
#pragma unroll
                for (int jq = 0; jq < 4; ++jq)
                    acc[i][jq] = fmaf(a[i], bb[jq], acc[i][jq]);
        }
        __syncthreads();
    }
    int o8 = obase + o8l, n4 = nbase + n4l;
#pragma unroll
    for (int i = 0; i < 8; ++i) {
        float bo = b4[o8 + i];
        float4 v;
        v.x = leaky(acc[i][0] + bo);
        v.y = leaky(acc[i][1] + bo);
        v.z = leaky(acc[i][2] + bo);
        v.w = leaky(acc[i][3] + bo);
        *(float4*)(out + ((long)(b * 256 + o8 + i)) * NPTS + n4) = v;
    }
}

extern "C" void kernel_launch(void* const* d_in, const int* in_sizes, int n_in,
                              void* d_out, int out_size) {
    const float* x  = (const float*)d_in[0];
    const float* W1 = (const float*)d_in[1];
    const float* b1 = (const float*)d_in[2];
    const float* W2 = (const float*)d_in[3];
    const float* b2 = (const float*)d_in[4];
    const float* W3 = (const float*)d_in[5];
    const float* b3 = (const float*)d_in[6];
    const float* W4 = (const float*)d_in[7];
    const float* b4 = (const float*)d_in[8];
    float* out = (float*)d_out;

    xx_kernel<<<64, 256>>>(x);
    knn_kernel<<<dim3(256, 2), 256>>>(x);
    pre1_kernel<<<4096, 256>>>(x, W1);
    conv1_kernel<<<dim3(1024, 2), 256>>>(x, W1, b1);
    preC_kernel<<<512, 256>>>(W2, b2, 0);
    convG_kernel<<<dim3(1024, 2), 256>>>(64);
    preC_kernel<<<512, 256>>>(W3, b3, 64);
    convG_kernel<<<dim3(1024, 2), 256>>>(128);
    final_kernel<<<dim3(64, 4, 2), 256>>>(W4, b4, out);
}